// round 7
// baseline (speedup 1.0000x reference)
#include <cuda_runtime.h>
#include <stdint.h>
#include <math.h>

// Problem constants
#define BB 8
#define NN 262144
#define CC 23
#define GG 10

#define THREADS 256
#define ROWS_PER_THREAD 4                      // 4 rows = 92 floats = 23 float4s
#define ROWS_PER_BLOCK (THREADS * ROWS_PER_THREAD)   // 1024
#define BLOCKS_PER_B (NN / ROWS_PER_BLOCK)     // 256
#define GRID (BB * BLOCKS_PER_B)               // 2048

// Scratch (no device allocation allowed -> static globals).
__device__ float g_partial[GRID * GG];         // 20480 floats
__device__ unsigned g_ticket;                  // zero-init; reset by last block

// group id for each of the 23 old columns
__device__ __constant__ int GRP[CC] = {0,0,1,1,2,2,2,3,3,4,4,4,5,5,6,6,6,7,7,8,8,9,9};

__global__ __launch_bounds__(THREADS) void fused_kernel(const float* __restrict__ inp,
                                                        const float* __restrict__ targets,
                                                        float* __restrict__ out) {
    __shared__ float wsum[THREADS / 32][GG];
    __shared__ float avg[BB * GG];
    __shared__ float klb[BB];
    __shared__ unsigned s_islast;

    const int tid = threadIdx.x;
    const int lane = tid & 31;
    const int warp = tid >> 5;

    // This thread's 4 rows start here (row index within the full 2M-row space).
    const size_t base_elem = ((size_t)blockIdx.x * ROWS_PER_BLOCK + (size_t)tid * ROWS_PER_THREAD) * CC;
    const float4* __restrict__ src = reinterpret_cast<const float4*>(inp + base_elem);

    // Load 23 float4s (92 floats = 4 rows) with streaming hint; independent -> high MLP.
    float4 w[23];
    #pragma unroll
    for (int i = 0; i < 23; i++) w[i] = __ldcs(&src[i]);

    float acc[GG];
    #pragma unroll
    for (int g = 0; g < GG; g++) acc[g] = 0.f;

    // Compile-time unrolled scatter: flat element 4i+j -> row (flat/23), col (flat%23).
    float cur[GG];
    #pragma unroll
    for (int g = 0; g < GG; g++) cur[g] = 0.f;

    #pragma unroll
    for (int i = 0; i < 23; i++) {
        const float e[4] = {w[i].x, w[i].y, w[i].z, w[i].w};
        #pragma unroll
        for (int j = 0; j < 4; j++) {
            const int flat = 4 * i + j;
            const int col = flat % CC;           // compile-time constants after unroll
            cur[GRP[col]] += e[j];
            if (col == CC - 1) {
                // row complete: normalize and accumulate
                float total = 0.f;
                #pragma unroll
                for (int g = 0; g < GG; g++) total += cur[g];
                const float inv = 1.0f / total;
                #pragma unroll
                for (int g = 0; g < GG; g++) { acc[g] += cur[g] * inv; cur[g] = 0.f; }
            }
        }
    }

    // Block reduction: warp shuffle then per-warp SMEM (deterministic, no atomics).
    #pragma unroll
    for (int g = 0; g < GG; g++) {
        float x = acc[g];
        x += __shfl_down_sync(0xffffffffu, x, 16);
        x += __shfl_down_sync(0xffffffffu, x, 8);
        x += __shfl_down_sync(0xffffffffu, x, 4);
        x += __shfl_down_sync(0xffffffffu, x, 2);
        x += __shfl_down_sync(0xffffffffu, x, 1);
        if (lane == 0) wsum[warp][g] = x;
    }
    __syncthreads();
    if (tid < GG) {
        float s = 0.f;
        #pragma unroll
        for (int wdx = 0; wdx < THREADS / 32; wdx++) s += wsum[wdx][tid];
        g_partial[blockIdx.x * GG + tid] = s;
    }

    // ---- last-block-done: final block reduces everything in-kernel ----
    __threadfence();
    if (tid == 0)
        s_islast = (atomicAdd(&g_ticket, 1u) == GRID - 1u);
    __syncthreads();
    if (!s_islast) return;
    __threadfence();

    // 80 (b,g) tasks over 8 warps -> 10 per warp. Each lane sums 8 partials
    // (stride 32 blocks) directly from global; all loads independent.
    #pragma unroll
    for (int k = 0; k < GG; k++) {
        const int t = warp * GG + k;             // 0..79
        const int tb = t / GG;
        const int tg = t % GG;
        const int blk0 = tb * BLOCKS_PER_B;
        float x = 0.f;
        #pragma unroll
        for (int j = 0; j < BLOCKS_PER_B / 32; j++)   // 8 loads
            x += g_partial[(blk0 + lane + 32 * j) * GG + tg];
        x += __shfl_down_sync(0xffffffffu, x, 16);
        x += __shfl_down_sync(0xffffffffu, x, 8);
        x += __shfl_down_sync(0xffffffffu, x, 4);
        x += __shfl_down_sync(0xffffffffu, x, 2);
        x += __shfl_down_sync(0xffffffffu, x, 1);
        if (lane == 0) avg[t] = x * (1.0f / (float)NN);
    }
    __syncthreads();

    if (tid < BB) {
        float kl = 0.f;
        #pragma unroll
        for (int g = 0; g < GG; g++) {
            const float tg = targets[tid * GG + g];
            kl += tg * (logf(tg) - logf(avg[tid * GG + g]));
        }
        klb[tid] = kl;
    }
    __syncthreads();

    if (tid == 0) {
        float s = 0.f;
        #pragma unroll
        for (int bb = 0; bb < BB; bb++) s += klb[bb];
        out[0] = s / (float)(GG * BB);
        g_ticket = 0;                            // reset for next graph replay
    }
}

extern "C" void kernel_launch(void* const* d_in, const int* in_sizes, int n_in,
                              void* d_out, int out_size) {
    const float* inp = (const float*)d_in[0];
    const float* tgt = (const float*)d_in[1];
    if (n_in >= 2 && in_sizes[0] == BB * GG) {   // defensive order check
        inp = (const float*)d_in[1];
        tgt = (const float*)d_in[0];
    }
    fused_kernel<<<GRID, THREADS>>>(inp, tgt, (float*)d_out);
}

// round 9
// speedup vs baseline: 2.1708x; 2.1708x over previous
#include <cuda_runtime.h>
#include <stdint.h>
#include <math.h>

// Problem constants
#define BB 8
#define NN 262144
#define CC 23
#define GG 10

#define THREADS 256
#define STAGE_ROWS 128
#define NSTAGES 4
#define STAGES_PER_BLOCK 16
#define ROWS_PER_BLOCK (STAGE_ROWS * STAGES_PER_BLOCK)  // 2048
#define CHUNKS (NN / ROWS_PER_BLOCK)                    // 128
#define GRID (BB * CHUNKS)                              // 1024
#define STAGE_FLOATS (STAGE_ROWS * CC)                  // 2944
#define STAGE_VEC4 (STAGE_FLOATS / 4)                   // 736

// Scratch (no device allocation allowed -> static globals).
__device__ float g_partial[GRID * GG];
__device__ unsigned g_ticket;   // zero-init; reset by last block each call

__device__ __forceinline__ unsigned smem_u32(const void* p) {
    unsigned a;
    asm("{ .reg .u64 t; cvta.to.shared.u64 t, %1; cvt.u32.u64 %0, t; }" : "=r"(a) : "l"(p));
    return a;
}

__global__ __launch_bounds__(THREADS, 4) void fused_kernel(const float* __restrict__ inp,
                                                           const float* __restrict__ targets,
                                                           float* __restrict__ out) {
    __shared__ float tile[NSTAGES][STAGE_FLOATS];   // 47104 B (static, < 48 KB)
    __shared__ float wsum[THREADS / 32][GG];
    __shared__ float avg[BB * GG];
    __shared__ float klb[BB];
    __shared__ unsigned s_islast;

    const int tid = threadIdx.x;
    const int lane = tid & 31;
    const int warp = tid >> 5;
    const int b = blockIdx.x >> 7;        // / CHUNKS
    const int chunk = blockIdx.x & 127;   // % CHUNKS
    const size_t row_base = (size_t)b * NN + (size_t)chunk * ROWS_PER_BLOCK;

    unsigned sbuf[NSTAGES];
    #pragma unroll
    for (int i = 0; i < NSTAGES; i++) sbuf[i] = smem_u32(&tile[i][0]);

    auto issue_stage = [&](int s) {
        const float4* __restrict__ src =
            reinterpret_cast<const float4*>(inp + (row_base + (size_t)s * STAGE_ROWS) * CC);
        const unsigned dst = sbuf[s & 3];
        #pragma unroll
        for (int i = tid; i < STAGE_VEC4; i += THREADS) {
            asm volatile("cp.async.cg.shared.global [%0], [%1], 16;"
                         :: "r"(dst + (unsigned)i * 16), "l"(src + i));
        }
        asm volatile("cp.async.commit_group;");
    };

    float a0 = 0.f, a1 = 0.f, a2 = 0.f, a3 = 0.f, a4 = 0.f;
    float a5 = 0.f, a6 = 0.f, a7 = 0.f, a8 = 0.f, a9 = 0.f;

    issue_stage(0);
    issue_stage(1);
    issue_stage(2);

    for (int s = 0; s < STAGES_PER_BLOCK; s++) {
        // Wait for group s to complete (outstanding after this wait: committed-after-s).
        if (s <= STAGES_PER_BLOCK - 3)      asm volatile("cp.async.wait_group 2;");
        else if (s == STAGES_PER_BLOCK - 2) asm volatile("cp.async.wait_group 1;");
        else                                asm volatile("cp.async.wait_group 0;");
        __syncthreads();   // everyone's group-s copies visible; buffer (s-1)&3 consumed

        if (s + 3 < STAGES_PER_BLOCK)
            issue_stage(s + 3);             // overwrites buffer (s-1)&3 — safe after sync

        if (tid < STAGE_ROWS) {
            // One row per thread; stride-23 across lanes is bank-conflict-free.
            const float* row = &tile[s & 3][tid * CC];
            float v[CC];
            #pragma unroll
            for (int c = 0; c < CC; c++) v[c] = row[c];

            const float s0 = v[0] + v[1];
            const float s1 = v[2] + v[3];
            const float s2 = v[4] + v[5] + v[6];
            const float s3 = v[7] + v[8];
            const float s4 = v[9] + v[10] + v[11];
            const float s5 = v[12] + v[13];
            const float s6 = v[14] + v[15] + v[16];
            const float s7 = v[17] + v[18];
            const float s8 = v[19] + v[20];
            const float s9 = v[21] + v[22];

            const float total = ((s0 + s1) + (s2 + s3)) + ((s4 + s5) + (s6 + s7)) + (s8 + s9);
            const float inv = 1.0f / total;

            a0 += s0 * inv; a1 += s1 * inv; a2 += s2 * inv; a3 += s3 * inv; a4 += s4 * inv;
            a5 += s5 * inv; a6 += s6 * inv; a7 += s7 * inv; a8 += s8 * inv; a9 += s9 * inv;
        }
        // next iteration's wait+sync closes the loop (single barrier per stage)
    }

    // Block reduction: warp shuffle then per-warp SMEM (deterministic, no atomics).
    float acc[GG] = {a0, a1, a2, a3, a4, a5, a6, a7, a8, a9};
    #pragma unroll
    for (int g = 0; g < GG; g++) {
        float x = acc[g];
        x += __shfl_down_sync(0xffffffffu, x, 16);
        x += __shfl_down_sync(0xffffffffu, x, 8);
        x += __shfl_down_sync(0xffffffffu, x, 4);
        x += __shfl_down_sync(0xffffffffu, x, 2);
        x += __shfl_down_sync(0xffffffffu, x, 1);
        if (lane == 0) wsum[warp][g] = x;
    }
    __syncthreads();
    if (tid < GG) {
        float s = 0.f;
        #pragma unroll
        for (int w = 0; w < THREADS / 32; w++) s += wsum[w][tid];
        g_partial[blockIdx.x * GG + tid] = s;
    }

    // ---- last-block-done: final block reduces everything in-kernel ----
    __threadfence();
    if (tid == 0)
        s_islast = (atomicAdd(&g_ticket, 1u) == GRID - 1u);
    __syncthreads();
    if (!s_islast) return;
    __threadfence();

    // 80 (b,g) tasks over 8 warps -> 10 per warp; lane sums 4 partials (stride 32).
    #pragma unroll
    for (int k = 0; k < GG; k++) {
        const int t = warp * GG + k;             // 0..79
        const int tb = t / GG;
        const int tg = t % GG;
        const int blk0 = tb * CHUNKS;
        float x = g_partial[(blk0 + lane +  0) * GG + tg]
                + g_partial[(blk0 + lane + 32) * GG + tg]
                + g_partial[(blk0 + lane + 64) * GG + tg]
                + g_partial[(blk0 + lane + 96) * GG + tg];
        x += __shfl_down_sync(0xffffffffu, x, 16);
        x += __shfl_down_sync(0xffffffffu, x, 8);
        x += __shfl_down_sync(0xffffffffu, x, 4);
        x += __shfl_down_sync(0xffffffffu, x, 2);
        x += __shfl_down_sync(0xffffffffu, x, 1);
        if (lane == 0) avg[t] = x * (1.0f / (float)NN);
    }
    __syncthreads();

    if (tid < BB) {
        float kl = 0.f;
        #pragma unroll
        for (int g = 0; g < GG; g++) {
            const float tg = targets[tid * GG + g];
            kl += tg * (logf(tg) - logf(avg[tid * GG + g]));
        }
        klb[tid] = kl;
    }
    __syncthreads();

    if (tid == 0) {
        float s = 0.f;
        #pragma unroll
        for (int bb = 0; bb < BB; bb++) s += klb[bb];
        out[0] = s / (float)(GG * BB);
        g_ticket = 0;                            // reset for next graph replay
    }
}

extern "C" void kernel_launch(void* const* d_in, const int* in_sizes, int n_in,
                              void* d_out, int out_size) {
    const float* inp = (const float*)d_in[0];
    const float* tgt = (const float*)d_in[1];
    if (n_in >= 2 && in_sizes[0] == BB * GG) {   // defensive order check
        inp = (const float*)d_in[1];
        tgt = (const float*)d_in[0];
    }
    fused_kernel<<<GRID, THREADS>>>(inp, tgt, (float*)d_out);
}

// round 10
// speedup vs baseline: 2.2637x; 1.0428x over previous
#include <cuda_runtime.h>
#include <stdint.h>
#include <math.h>

// Problem constants
#define BB 8
#define NN 262144
#define CC 23
#define GG 10

#define THREADS 256
#define ITERS 16
#define ROWS_PER_BLOCK (THREADS * ITERS)      // 4096
#define CHUNKS (NN / ROWS_PER_BLOCK)          // 64
#define GRID (BB * CHUNKS)                    // 512  -> single wave (4 blocks/SM x 148 SMs)
#define TILE_FLOATS (THREADS * CC)            // 5888
#define TILE_VEC4 (TILE_FLOATS / 4)           // 1472

// Scratch (no device allocation allowed -> static globals).
__device__ float g_partial[GRID * GG];        // 5120 floats
__device__ unsigned g_ticket;                 // zero-init; reset by last block

__device__ __forceinline__ unsigned smem_u32(const void* p) {
    unsigned a;
    asm("{ .reg .u64 t; cvta.to.shared.u64 t, %1; cvt.u32.u64 %0, t; }" : "=r"(a) : "l"(p));
    return a;
}

__global__ __launch_bounds__(THREADS) void fused_kernel(const float* __restrict__ inp,
                                                        const float* __restrict__ targets,
                                                        float* __restrict__ out) {
    __shared__ float tile[2][TILE_FLOATS];     // 47104 B
    __shared__ float wsum[THREADS / 32][GG];
    __shared__ float avg[BB * GG];
    __shared__ float klb[BB];
    __shared__ unsigned s_islast;

    const int tid = threadIdx.x;
    const int lane = tid & 31;
    const int warp = tid >> 5;
    const int b = blockIdx.x >> 6;        // / CHUNKS
    const int chunk = blockIdx.x & 63;    // % CHUNKS
    const size_t row_base = (size_t)b * NN + (size_t)chunk * ROWS_PER_BLOCK;

    const unsigned sbuf0 = smem_u32(&tile[0][0]);
    const unsigned sbuf1 = smem_u32(&tile[1][0]);

    auto issue_tile = [&](int it, int buf) {
        const float4* __restrict__ src =
            reinterpret_cast<const float4*>(inp + (row_base + (size_t)it * THREADS) * CC);
        const unsigned s = buf ? sbuf1 : sbuf0;
        #pragma unroll
        for (int i = tid; i < TILE_VEC4; i += THREADS) {
            asm volatile("cp.async.cg.shared.global [%0], [%1], 16;"
                         :: "r"(s + (unsigned)i * 16), "l"(src + i));
        }
        asm volatile("cp.async.commit_group;");
    };

    float a0 = 0.f, a1 = 0.f, a2 = 0.f, a3 = 0.f, a4 = 0.f;
    float a5 = 0.f, a6 = 0.f, a7 = 0.f, a8 = 0.f, a9 = 0.f;

    issue_tile(0, 0);

    for (int it = 0; it < ITERS; it++) {
        if (it + 1 < ITERS) {
            issue_tile(it + 1, (it + 1) & 1);
            asm volatile("cp.async.wait_group 1;");
        } else {
            asm volatile("cp.async.wait_group 0;");
        }
        __syncthreads();

        // One row per thread from SMEM; stride-23 across lanes is bank-conflict-free.
        const float* row = &tile[it & 1][tid * CC];
        float v[CC];
        #pragma unroll
        for (int c = 0; c < CC; c++) v[c] = row[c];

        const float s0 = v[0] + v[1];
        const float s1 = v[2] + v[3];
        const float s2 = v[4] + v[5] + v[6];
        const float s3 = v[7] + v[8];
        const float s4 = v[9] + v[10] + v[11];
        const float s5 = v[12] + v[13];
        const float s6 = v[14] + v[15] + v[16];
        const float s7 = v[17] + v[18];
        const float s8 = v[19] + v[20];
        const float s9 = v[21] + v[22];

        const float total = ((s0 + s1) + (s2 + s3)) + ((s4 + s5) + (s6 + s7)) + (s8 + s9);
        const float inv = 1.0f / total;

        a0 += s0 * inv; a1 += s1 * inv; a2 += s2 * inv; a3 += s3 * inv; a4 += s4 * inv;
        a5 += s5 * inv; a6 += s6 * inv; a7 += s7 * inv; a8 += s8 * inv; a9 += s9 * inv;
        __syncthreads();   // buffer (it&1) safe to overwrite at next issue
    }

    // Block reduction: warp shuffle then per-warp SMEM (deterministic, no atomics).
    float acc[GG] = {a0, a1, a2, a3, a4, a5, a6, a7, a8, a9};
    #pragma unroll
    for (int g = 0; g < GG; g++) {
        float x = acc[g];
        x += __shfl_down_sync(0xffffffffu, x, 16);
        x += __shfl_down_sync(0xffffffffu, x, 8);
        x += __shfl_down_sync(0xffffffffu, x, 4);
        x += __shfl_down_sync(0xffffffffu, x, 2);
        x += __shfl_down_sync(0xffffffffu, x, 1);
        if (lane == 0) wsum[warp][g] = x;
    }
    __syncthreads();
    if (tid < GG) {
        float s = 0.f;
        #pragma unroll
        for (int w = 0; w < THREADS / 32; w++) s += wsum[w][tid];
        g_partial[blockIdx.x * GG + tid] = s;
    }

    // ---- last-block-done: final block reduces everything in-kernel ----
    __threadfence();
    if (tid == 0)
        s_islast = (atomicAdd(&g_ticket, 1u) == GRID - 1u);
    __syncthreads();
    if (!s_islast) return;
    __threadfence();

    // 80 (b,g) tasks over 8 warps -> 10 per warp; lane sums 2 partials (64 chunks).
    #pragma unroll
    for (int k = 0; k < GG; k++) {
        const int t = warp * GG + k;             // 0..79
        const int tb = t / GG;
        const int tg = t % GG;
        const int blk0 = tb * CHUNKS;
        float x = g_partial[(blk0 + lane +  0) * GG + tg]
                + g_partial[(blk0 + lane + 32) * GG + tg];
        x += __shfl_down_sync(0xffffffffu, x, 16);
        x += __shfl_down_sync(0xffffffffu, x, 8);
        x += __shfl_down_sync(0xffffffffu, x, 4);
        x += __shfl_down_sync(0xffffffffu, x, 2);
        x += __shfl_down_sync(0xffffffffu, x, 1);
        if (lane == 0) avg[t] = x * (1.0f / (float)NN);
    }
    __syncthreads();

    if (tid < BB) {
        float kl = 0.f;
        #pragma unroll
        for (int g = 0; g < GG; g++) {
            const float tg = targets[tid * GG + g];
            kl += tg * (logf(tg) - logf(avg[tid * GG + g]));
        }
        klb[tid] = kl;
    }
    __syncthreads();

    if (tid == 0) {
        float s = 0.f;
        #pragma unroll
        for (int bb = 0; bb < BB; bb++) s += klb[bb];
        out[0] = s / (float)(GG * BB);
        g_ticket = 0;                            // reset for next graph replay
    }
}

extern "C" void kernel_launch(void* const* d_in, const int* in_sizes, int n_in,
                              void* d_out, int out_size) {
    const float* inp = (const float*)d_in[0];
    const float* tgt = (const float*)d_in[1];
    if (n_in >= 2 && in_sizes[0] == BB * GG) {   // defensive order check
        inp = (const float*)d_in[1];
        tgt = (const float*)d_in[0];
    }
    fused_kernel<<<GRID, THREADS>>>(inp, tgt, (float*)d_out);
}